// round 15
// baseline (speedup 1.0000x reference)
#include <cuda_runtime.h>
#include <cuda_bf16.h>
#include <math.h>
#include <cstdint>

#define NN 50000
#define EE 640000

// ---------------- scratch (device globals; no allocation allowed) ----------------
__device__ __align__(16) float g_h_env[NN * 128];    // h for env layer
__device__ __align__(16) float g_num_env[NN * 128];  // env numerator accumulators
__device__ float g_Wenv[EE];  // exp(env logit) per edge
__device__ int g_elist[EE];   // compacted surviving env edges
__device__ int g_ecnt;

// packed per-node gather vectors
__device__ __align__(16) float4 g_dstv[NN];  // {sd_in, sd_out, sd_env, -}
struct __align__(32) SrcPack {
    float4 A;  // {ss_in, ss_out, h_in.x, h_in.y}
    float4 B;  // {ss_env, h_out.x, h_out.y, -}
};
__device__ SrcPack g_src[NN];

// packed per-node in/out accumulators (vector reductions land here)
struct __align__(32) AccIO {
    float4 a;  // {den_in, num_in.x, num_in.y, den_out}
    float2 b;  // {num_out.x, num_out.y}
    float2 pad;
};
__device__ AccIO g_accio[NN];

__device__ float2 g_res_in[NN], g_res_out[NN];
__device__ float g_den_env[NN];
__device__ unsigned char g_cin[NN], g_cout[NN];
__device__ float g_srel[6];  // (in,out,env) s_rel[t] + a_b, t in {0,1}

// ---------------- helpers ----------------
__device__ __forceinline__ float lrelu(float v) { return v >= 0.f ? v : 0.2f * v; }

__device__ __forceinline__ void red_add_v2(float* p, float a, float b) {
    asm volatile("red.global.add.v2.f32 [%0], {%1, %2};" ::"l"(p), "f"(a), "f"(b) : "memory");
}
__device__ __forceinline__ void red_add_v4(float* p, float a, float b, float c, float d) {
    asm volatile("red.global.add.v4.f32 [%0], {%1, %2, %3, %4};" ::"l"(p), "f"(a), "f"(b),
                 "f"(c), "f"(d)
                 : "memory");
}

__device__ __forceinline__ uint32_t smem_u32(const void* p) {
    uint32_t a;
    asm("{ .reg .u64 t; cvta.to.shared.u64 t, %1; cvt.u32.u64 %0, t; }" : "=r"(a) : "l"(p));
    return a;
}
__device__ __forceinline__ unsigned short f2b(float v) {
    return __bfloat16_as_ushort(__float2bfloat16_rn(v));
}
__device__ __forceinline__ void ldm4(uint32_t* r, uint32_t addr) {
    asm volatile("ldmatrix.sync.aligned.m8n8.x4.shared.b16 {%0,%1,%2,%3}, [%4];"
                 : "=r"(r[0]), "=r"(r[1]), "=r"(r[2]), "=r"(r[3])
                 : "r"(addr));
}
__device__ __forceinline__ void mma_bf16(float* c, const uint32_t* a, const uint32_t* b) {
    asm volatile(
        "mma.sync.aligned.m16n8k16.row.col.f32.bf16.bf16.f32 "
        "{%0,%1,%2,%3}, {%4,%5,%6,%7}, {%8,%9}, {%0,%1,%2,%3};"
        : "+f"(c[0]), "+f"(c[1]), "+f"(c[2]), "+f"(c[3])
        : "r"(a[0]), "r"(a[1]), "r"(a[2]), "r"(a[3]), "r"(b[0]), "r"(b[1]));
}

// ---------------- kernels ----------------
__global__ void k_init() {
    int i = blockIdx.x * blockDim.x + threadIdx.x;
    if (i < NN * 128) g_num_env[i] = 0.f;
    if (i < NN) {
        g_accio[i].a = make_float4(0.f, 0.f, 0.f, 0.f);
        g_accio[i].b = make_float2(0.f, 0.f);
        g_den_env[i] = 0.f;
    }
    if (i == 0) g_ecnt = 0;
}

// s_rel (+a_b) for all three layers.
__global__ void k_srel(const float* __restrict__ iWr, const float* __restrict__ iWrb,
                       const float* __restrict__ ia, const float* __restrict__ iab,
                       const float* __restrict__ irel, const float* __restrict__ oWr,
                       const float* __restrict__ oWrb, const float* __restrict__ oa,
                       const float* __restrict__ oab, const float* __restrict__ orel,
                       const float* __restrict__ eWr, const float* __restrict__ eWrb,
                       const float* __restrict__ ea, const float* __restrict__ eab,
                       const float* __restrict__ erel) {
    __shared__ float red[128];
    int j = threadIdx.x;
    for (int t = 0; t < 2; t++) {
        float r = eWrb[j];
        for (int k = 0; k < 100; k++) r += erel[t * 100 + k] * eWr[j * 100 + k];
        red[j] = r * ea[256 + j];
        __syncthreads();
        for (int s = 64; s > 0; s >>= 1) {
            if (j < s) red[j] += red[j + s];
            __syncthreads();
        }
        if (j == 0) g_srel[4 + t] = red[0] + eab[0];
        __syncthreads();
    }
    if (j == 0) {
        for (int t = 0; t < 2; t++) {
            float r0 = iWrb[0], r1 = iWrb[1];
            for (int k = 0; k < 100; k++) {
                r0 += irel[t * 100 + k] * iWr[k];
                r1 += irel[t * 100 + k] * iWr[100 + k];
            }
            g_srel[t] = r0 * ia[4] + r1 * ia[5] + iab[0];
            float q0 = oWrb[0], q1 = oWrb[1];
            for (int k = 0; k < 100; k++) {
                q0 += orel[t * 100 + k] * oWr[k];
                q1 += orel[t * 100 + k] * oWr[100 + k];
            }
            g_srel[2 + t] = q0 * oa[4] + q1 * oa[5] + oab[0];
        }
    }
}

// per-node small layers (inA / outA). Writes ONLY the fields it owns (scalar
// stores) so it can run concurrently with k_mma, which owns dstv.z and src.B.x.
__global__ void k_node_small(const float* __restrict__ x, const float* __restrict__ iW,
                             const float* __restrict__ iWb, const float* __restrict__ ia,
                             const float* __restrict__ iRw, const float* __restrict__ iRb,
                             const float* __restrict__ oW, const float* __restrict__ oWb,
                             const float* __restrict__ oa, const float* __restrict__ oRw,
                             const float* __restrict__ oRb) {
    int warp = (blockIdx.x * blockDim.x + threadIdx.x) >> 5;
    int lane = threadIdx.x & 31;
    if (warp >= NN) return;
    float4 xv = *(const float4*)(x + warp * 128 + lane * 4);
    auto dotw = [&](const float* w) {
        float4 wv = *(const float4*)(w + lane * 4);
        return xv.x * wv.x + xv.y * wv.y + xv.z * wv.z + xv.w * wv.w;
    };
    float d0 = dotw(iW), d1 = dotw(iW + 128);
    float d2 = dotw(iRw), d3 = dotw(iRw + 128);
    float d4 = dotw(oW), d5 = dotw(oW + 128);
    float d6 = dotw(oRw), d7 = dotw(oRw + 128);
    auto wred = [&](float v) {
        for (int o = 16; o > 0; o >>= 1) v += __shfl_xor_sync(0xffffffffu, v, o);
        return v;
    };
    d0 = wred(d0); d1 = wred(d1); d2 = wred(d2); d3 = wred(d3);
    d4 = wred(d4); d5 = wred(d5); d6 = wred(d6); d7 = wred(d7);
    if (lane == 0) {
        float h0 = d0 + iWb[0], h1 = d1 + iWb[1];
        float p0 = d4 + oWb[0], p1 = d5 + oWb[1];
        float* dv = (float*)(g_dstv + warp);
        dv[0] = h0 * ia[0] + h1 * ia[1];
        dv[1] = p0 * oa[0] + p1 * oa[1];
        g_src[warp].A = make_float4(h0 * ia[2] + h1 * ia[3], p0 * oa[2] + p1 * oa[3], h0, h1);
        float* sB = (float*)&g_src[warp].B;
        sB[1] = p0;
        sB[2] = p1;
        g_res_in[warp] = make_float2(d2 + iRb[0], d3 + iRb[1]);
        g_res_out[warp] = make_float2(d6 + oRb[0], d7 + oRb[1]);
    }
}

// ---------------- tensor-core env GEMMs (bf16x3 via warp mma.sync, fused) ----------------
// One CTA (512 threads, 16 warps): converts A once, runs h_env = x@W^T+b (+ fused
// s_env) AND d_out = x@Wres^T+b. D = A_hi*B_hi + A_hi*B_lo + A_lo*B_hi.
#define OFF_BW 64
#define OFF_BR 576
#define OFF_A1 1088
#define OFF_A2 1600
#define OFF_AHI 2176
#define TILE_B (128 * 272)  // 128 rows x (128 bf16 + 8 pad) = 34816 B
#define OFF_ALO (OFF_AHI + TILE_B)
#define OFF_WHI (OFF_ALO + TILE_B)
#define OFF_WLO (OFF_WHI + TILE_B)
#define OFF_RHI (OFF_WLO + TILE_B)
#define OFF_RLO (OFF_RHI + TILE_B)
#define OFF_SD (OFF_RLO + TILE_B)  // 128*4 floats = 2048 B
#define OFF_SS (OFF_SD + 2048)     // 128*4 floats = 2048 B
#define SMEM_MMA (OFF_SS + 2048)

__device__ __forceinline__ void cvt_tile(const float* __restrict__ T, char* smem, int off_hi,
                                         int off_lo, int tid, int m0, bool guard) {
#pragma unroll
    for (int i = 0; i < 8; i++) {
        int f = i * 512 + tid;  // float4 index in 128x32
        int row = f >> 5;
        int c4 = f & 31;
        float4 v;
        if (guard) {
            int gm = m0 + row;
            v = (gm < NN) ? *(const float4*)(T + (long)gm * 128 + c4 * 4)
                          : make_float4(0.f, 0.f, 0.f, 0.f);
        } else {
            v = *(const float4*)(T + (long)row * 128 + c4 * 4);
        }
        unsigned short h0 = f2b(v.x), h1 = f2b(v.y), h2 = f2b(v.z), h3 = f2b(v.w);
        uint32_t hi01 = (uint32_t)h0 | ((uint32_t)h1 << 16);
        uint32_t hi23 = (uint32_t)h2 | ((uint32_t)h3 << 16);
        uint32_t lo01 = (uint32_t)f2b(v.x - __bfloat162float(__ushort_as_bfloat16(h0))) |
                        ((uint32_t)f2b(v.y - __bfloat162float(__ushort_as_bfloat16(h1))) << 16);
        uint32_t lo23 = (uint32_t)f2b(v.z - __bfloat162float(__ushort_as_bfloat16(h2))) |
                        ((uint32_t)f2b(v.w - __bfloat162float(__ushort_as_bfloat16(h3))) << 16);
        char* p = smem + row * 272 + c4 * 8;
        *(uint32_t*)(p + off_hi) = hi01;
        *(uint32_t*)(p + off_hi + 4) = hi23;
        *(uint32_t*)(p + off_lo) = lo01;
        *(uint32_t*)(p + off_lo + 4) = lo23;
    }
}

__global__ void __launch_bounds__(512, 1)
k_mma(const float* __restrict__ A, const float* __restrict__ W0, const float* __restrict__ b0,
      const float* __restrict__ W1, const float* __restrict__ b1, float* __restrict__ Cout,
      const float* __restrict__ ea) {
    extern __shared__ char smem[];
    const int m0 = blockIdx.x * 128;
    const int tid = threadIdx.x;
    const int wid = tid >> 5;
    const int lane = tid & 31;

    float* bw_s = (float*)(smem + OFF_BW);
    float* br_s = (float*)(smem + OFF_BR);
    float* a1_s = (float*)(smem + OFF_A1);
    float* a2_s = (float*)(smem + OFF_A2);
    if (tid < 128) {
        bw_s[tid] = b0[tid];
        br_s[tid] = b1[tid];
        a1_s[tid] = ea[tid];
        a2_s[tid] = ea[128 + tid];
    }

    cvt_tile(A, smem, OFF_AHI, OFF_ALO, tid, m0, true);
    cvt_tile(W0, smem, OFF_WHI, OFF_WLO, tid, 0, false);
    cvt_tile(W1, smem, OFF_RHI, OFF_RLO, tid, 0, false);
    __syncthreads();

    // warp layout: 4 (m) x 4 (n); warp tile 32x32
    const int wm = wid >> 2;
    const int wn = wid & 3;
    const uint32_t sb = smem_u32(smem);
    const int a_row = lane & 15;
    const int a_kb = (lane >> 4) * 16;
    const int b_n = (lane & 7) + ((lane >> 4) << 3);
    const int b_kb = ((lane >> 3) & 1) * 16;
    const int fr = lane >> 2;
    const int fc = (lane & 3) * 2;

    float* sdbuf = (float*)(smem + OFF_SD);
    float* ssbuf = (float*)(smem + OFF_SS);

#pragma unroll
    for (int gemm = 0; gemm < 2; gemm++) {
        const bool env = (gemm == 0);
        float* C = env ? g_h_env : Cout;
        const float* bias_s = env ? bw_s : br_s;
        const int off_bh = env ? OFF_WHI : OFF_RHI;
        const int off_bl = env ? OFF_WLO : OFF_RLO;

        float acc[2][4][4];
#pragma unroll
        for (int ms = 0; ms < 2; ms++)
#pragma unroll
            for (int ns = 0; ns < 4; ns++)
#pragma unroll
                for (int q = 0; q < 4; q++) acc[ms][ns][q] = 0.f;

#pragma unroll
        for (int pass = 0; pass < 3; pass++) {
            const uint32_t abase = sb + (pass == 2 ? OFF_ALO : OFF_AHI);
            const uint32_t bbase = sb + (pass == 1 ? off_bl : off_bh);
#pragma unroll
            for (int kk = 0; kk < 8; kk++) {
                uint32_t af[2][4];
#pragma unroll
                for (int ms = 0; ms < 2; ms++) {
                    uint32_t addr = abase + (wm * 32 + ms * 16 + a_row) * 272 + kk * 32 + a_kb;
                    ldm4(af[ms], addr);
                }
                uint32_t bf[4][2];
#pragma unroll
                for (int np = 0; np < 2; np++) {
                    uint32_t addr = bbase + (wn * 32 + np * 16 + b_n) * 272 + kk * 32 + b_kb;
                    uint32_t r[4];
                    ldm4(r, addr);
                    bf[np * 2][0] = r[0];
                    bf[np * 2][1] = r[1];
                    bf[np * 2 + 1][0] = r[2];
                    bf[np * 2 + 1][1] = r[3];
                }
#pragma unroll
                for (int ms = 0; ms < 2; ms++)
#pragma unroll
                    for (int ns = 0; ns < 4; ns++) mma_bf16(acc[ms][ns], af[ms], bf[ns]);
            }
        }

        // epilogue: bias + direct float2 stores (quad-contiguous 32B sectors) + fused dots
#pragma unroll
        for (int ms = 0; ms < 2; ms++) {
#pragma unroll
            for (int h = 0; h < 2; h++) {
                int row = wm * 32 + ms * 16 + h * 8 + fr;
                int gm = m0 + row;
                float sd = 0.f, ss = 0.f;
#pragma unroll
                for (int ns = 0; ns < 4; ns++) {
                    int col = wn * 32 + ns * 8 + fc;
                    float v0 = acc[ms][ns][h * 2 + 0] + bias_s[col];
                    float v1 = acc[ms][ns][h * 2 + 1] + bias_s[col + 1];
                    if (gm < NN) {
                        float2 st = make_float2(v0, v1);
                        *(float2*)(C + (long)gm * 128 + col) = st;
                    }
                    if (env) {
                        sd += v0 * a1_s[col] + v1 * a1_s[col + 1];
                        ss += v0 * a2_s[col] + v1 * a2_s[col + 1];
                    }
                }
                if (env) {
                    sd += __shfl_xor_sync(0xffffffffu, sd, 1);
                    sd += __shfl_xor_sync(0xffffffffu, sd, 2);
                    ss += __shfl_xor_sync(0xffffffffu, ss, 1);
                    ss += __shfl_xor_sync(0xffffffffu, ss, 2);
                    if ((lane & 3) == 0) {
                        sdbuf[row * 4 + wn] = sd;
                        ssbuf[row * 4 + wn] = ss;
                    }
                }
            }
        }
        if (env) {
            __syncthreads();
            if (tid < 128 && m0 + tid < NN) {
                float sd = sdbuf[tid * 4] + sdbuf[tid * 4 + 1] + sdbuf[tid * 4 + 2] +
                           sdbuf[tid * 4 + 3];
                float ss = ssbuf[tid * 4] + ssbuf[tid * 4 + 1] + ssbuf[tid * 4 + 2] +
                           ssbuf[tid * 4 + 3];
                ((float*)(g_dstv + m0 + tid))[2] = sd;
                ((float*)&g_src[m0 + tid].B)[0] = ss;
            }
        }
    }
}

// Fused edge pass: logits for all three layers, exp (shift-free softmax —
// alpha = e/sum(e) is shift-invariant and |logit| is small), vector scatter-reduce.
__global__ void k_edge_fused(const int* __restrict__ ei, const int* __restrict__ et) {
    int e = blockIdx.x * blockDim.x + threadIdx.x;
    if (e >= EE) return;
    float s0 = g_srel[0], s1 = g_srel[1], s2 = g_srel[2];
    float s3 = g_srel[3], s4 = g_srel[4], s5 = g_srel[5];
    int src = ei[e];
    int dst = ei[EE + e];
    int t = et[e];
    float4 dv = g_dstv[dst];
    float4 sa = g_src[src].A;
    float4 sb = g_src[src].B;
    float win = expf(lrelu(dv.x + sa.x + (t ? s1 : s0)));
    float wout = expf(lrelu(dv.y + sa.y + (t ? s3 : s2)));
    float wenv = expf(lrelu(dv.z + sb.x + (t ? s5 : s4)));
    red_add_v4(&g_accio[dst].a.x, win, sa.z * win, sa.w * win, wout);
    red_add_v2(&g_accio[dst].b.x, sb.y * wout, sb.z * wout);
    g_Wenv[e] = wenv;
}

// gumbel-hard choices
__global__ void k_choice(const float* __restrict__ gin, const float* __restrict__ gout) {
    int i = blockIdx.x * blockDim.x + threadIdx.x;
    if (i >= NN) return;
    float4 a = g_accio[i].a;
    float2 b = g_accio[i].b;
    {
        float dn = fmaxf(a.x, 1e-16f);
        float2 rs = g_res_in[i];
        float z0 = a.y / dn + rs.x + gin[2 * i];
        float z1 = a.z / dn + rs.y + gin[2 * i + 1];
        g_cin[i] = (z0 >= z1) ? 1 : 0;
    }
    {
        float dn = fmaxf(a.w, 1e-16f);
        float2 rs = g_res_out[i];
        float z0 = b.x / dn + rs.x + gout[2 * i];
        float z1 = b.y / dn + rs.y + gout[2 * i + 1];
        g_cout[i] = (z0 >= z1) ? 1 : 0;
    }
}

// env: apply mask, accumulate denominator, compact survivors
__global__ void k_edge_mask(const int* __restrict__ ei) {
    int e = blockIdx.x * blockDim.x + threadIdx.x;
    bool keep = false;
    if (e < EE) {
        int src = ei[e];
        int dst = ei[EE + e];
        keep = g_cin[dst] && g_cout[src];
        if (keep) atomicAdd(&g_den_env[dst], g_Wenv[e]);
    }
    unsigned bal = __ballot_sync(0xffffffffu, keep);
    if (keep) {
        int lane = threadIdx.x & 31;
        int leader = __ffs(bal) - 1;
        int base;
        if (lane == leader) base = atomicAdd(&g_ecnt, __popc(bal));
        base = __shfl_sync(bal, base, leader);
        int off = __popc(bal & ((1u << lane) - 1u));
        g_elist[base + off] = e;
    }
}

// env aggregation over compacted edges: warp per edge, persistent grid-stride
__global__ void k_edge_aggr(const int* __restrict__ ei) {
    const int cnt = g_ecnt;
    int warp = (blockIdx.x * blockDim.x + threadIdx.x) >> 5;
    const int nwarps = (gridDim.x * blockDim.x) >> 5;
    const int lane = threadIdx.x & 31;
    for (int i = warp; i < cnt; i += nwarps) {
        int e = g_elist[i];
        int src = ei[e];
        int dst = ei[EE + e];
        float w = g_Wenv[e];
        float4 hv = *(const float4*)(g_h_env + (long)src * 128 + lane * 4);
        red_add_v4(g_num_env + (long)dst * 128 + lane * 4, hv.x * w, hv.y * w, hv.z * w,
                   hv.w * w);
    }
}

// out = res (already in d_out) + num/max(den,1e-16)
__global__ void k_final(float* __restrict__ out) {
    int idx = blockIdx.x * blockDim.x + threadIdx.x;
    if (idx >= NN * 32) return;
    int node = idx >> 5;
    float inv = 1.f / fmaxf(g_den_env[node], 1e-16f);
    float4 nm = ((const float4*)g_num_env)[idx];
    float4 o = ((float4*)out)[idx];
    o.x += nm.x * inv;
    o.y += nm.y * inv;
    o.z += nm.z * inv;
    o.w += nm.w * inv;
    ((float4*)out)[idx] = o;
}

// ---------------- launch ----------------
extern "C" void kernel_launch(void* const* d_in, const int* in_sizes, int n_in, void* d_out,
                              int out_size) {
    const float* x = (const float*)d_in[0];
    const int* ei = (const int*)d_in[1];
    const int* et = (const int*)d_in[2];
    const float* gin = (const float*)d_in[3];
    const float* gout = (const float*)d_in[4];
    const float* iW = (const float*)d_in[5];
    const float* iWb = (const float*)d_in[6];
    const float* ia = (const float*)d_in[9];
    const float* iRw = (const float*)d_in[11];
    const float* iRb = (const float*)d_in[12];
    const float* oW = (const float*)d_in[14];
    const float* oWb = (const float*)d_in[15];
    const float* oa = (const float*)d_in[18];
    const float* oRw = (const float*)d_in[20];
    const float* oRb = (const float*)d_in[21];
    const float* eW = (const float*)d_in[23];
    const float* eWb = (const float*)d_in[24];
    const float* ea = (const float*)d_in[27];
    const float* eRw = (const float*)d_in[29];
    const float* eRb = (const float*)d_in[30];
    float* out = (float*)d_out;

    static cudaStream_t s1 = nullptr;
    static cudaEvent_t evFork = nullptr, evJoin = nullptr;
    if (s1 == nullptr) {
        cudaStreamCreateWithFlags(&s1, cudaStreamNonBlocking);
        cudaEventCreateWithFlags(&evFork, cudaEventDisableTiming);
        cudaEventCreateWithFlags(&evJoin, cudaEventDisableTiming);
        cudaFuncSetAttribute(k_mma, cudaFuncAttributeMaxDynamicSharedMemorySize, SMEM_MMA);
    }

    // fork: front-end (init/srel/node_small) runs on s1 concurrently with k_mma
    cudaEventRecord(evFork, 0);
    cudaStreamWaitEvent(s1, evFork, 0);
    k_init<<<(NN * 128 + 255) / 256, 256, 0, s1>>>();
    k_srel<<<1, 128, 0, s1>>>((const float*)d_in[7], (const float*)d_in[8], ia,
                              (const float*)d_in[10], (const float*)d_in[13],
                              (const float*)d_in[16], (const float*)d_in[17], oa,
                              (const float*)d_in[19], (const float*)d_in[22],
                              (const float*)d_in[25], (const float*)d_in[26], ea,
                              (const float*)d_in[28], (const float*)d_in[31]);
    k_node_small<<<(NN + 7) / 8, 256, 0, s1>>>(x, iW, iWb, ia, iRw, iRb, oW, oWb, oa, oRw,
                                               oRb);
    cudaEventRecord(evJoin, s1);

    k_mma<<<(NN + 127) / 128, 512, SMEM_MMA>>>(x, eW, eWb, eRw, eRb, out, ea);
    cudaStreamWaitEvent(0, evJoin, 0);

    k_edge_fused<<<(EE + 255) / 256, 256>>>(ei, et);
    k_choice<<<(NN + 255) / 256, 256>>>(gin, gout);
    k_edge_mask<<<(EE + 255) / 256, 256>>>(ei);
    k_edge_aggr<<<2048, 256>>>(ei);
    k_final<<<(NN * 32 + 255) / 256, 256>>>(out);
}

// round 16
// speedup vs baseline: 1.0757x; 1.0757x over previous
#include <cuda_runtime.h>
#include <cuda_bf16.h>
#include <math.h>
#include <cstdint>

#define NN 50000
#define EE 640000

// ---------------- scratch (device globals; no allocation allowed) ----------------
__device__ __align__(16) float g_h_env[NN * 128];    // h for env layer
__device__ __align__(16) float g_num_env[NN * 128];  // env numerator accumulators
__device__ float g_Wenv[EE];  // exp(env logit) per edge
__device__ int g_elist[EE];   // compacted surviving env edges
__device__ int g_ecnt;

// packed per-node gather vectors
__device__ __align__(16) float4 g_dstv[NN];  // {sd_in, sd_out, sd_env, -}
struct __align__(32) SrcPack {
    float4 A;  // {ss_in, ss_out, h_in.x, h_in.y}
    float4 B;  // {ss_env, h_out.x, h_out.y, -}
};
__device__ SrcPack g_src[NN];

// packed per-node in/out accumulators (vector reductions land here)
struct __align__(32) AccIO {
    float4 a;  // {den_in, num_in.x, num_in.y, den_out}
    float2 b;  // {num_out.x, num_out.y}
    float2 pad;
};
__device__ AccIO g_accio[NN];

__device__ float2 g_res_in[NN], g_res_out[NN];
__device__ float g_den_env[NN];
__device__ unsigned char g_cin[NN], g_cout[NN];
__device__ float g_srel[6];  // (in,out,env) s_rel[t] + a_b, t in {0,1}

// ---------------- helpers ----------------
__device__ __forceinline__ float lrelu(float v) { return v >= 0.f ? v : 0.2f * v; }

__device__ __forceinline__ void red_add_v2(float* p, float a, float b) {
    asm volatile("red.global.add.v2.f32 [%0], {%1, %2};" ::"l"(p), "f"(a), "f"(b) : "memory");
}
__device__ __forceinline__ void red_add_v4(float* p, float a, float b, float c, float d) {
    asm volatile("red.global.add.v4.f32 [%0], {%1, %2, %3, %4};" ::"l"(p), "f"(a), "f"(b),
                 "f"(c), "f"(d)
                 : "memory");
}

__device__ __forceinline__ uint32_t smem_u32(const void* p) {
    uint32_t a;
    asm("{ .reg .u64 t; cvta.to.shared.u64 t, %1; cvt.u32.u64 %0, t; }" : "=r"(a) : "l"(p));
    return a;
}
__device__ __forceinline__ unsigned short f2b(float v) {
    return __bfloat16_as_ushort(__float2bfloat16_rn(v));
}
__device__ __forceinline__ void ldm4(uint32_t* r, uint32_t addr) {
    asm volatile("ldmatrix.sync.aligned.m8n8.x4.shared.b16 {%0,%1,%2,%3}, [%4];"
                 : "=r"(r[0]), "=r"(r[1]), "=r"(r[2]), "=r"(r[3])
                 : "r"(addr));
}
__device__ __forceinline__ void mma_bf16(float* c, const uint32_t* a, const uint32_t* b) {
    asm volatile(
        "mma.sync.aligned.m16n8k16.row.col.f32.bf16.bf16.f32 "
        "{%0,%1,%2,%3}, {%4,%5,%6,%7}, {%8,%9}, {%0,%1,%2,%3};"
        : "+f"(c[0]), "+f"(c[1]), "+f"(c[2]), "+f"(c[3])
        : "r"(a[0]), "r"(a[1]), "r"(a[2]), "r"(a[3]), "r"(b[0]), "r"(b[1]));
}

// ---------------- kernels ----------------
__global__ void k_init() {
    int i = blockIdx.x * blockDim.x + threadIdx.x;
    if (i < NN * 128) g_num_env[i] = 0.f;
    if (i < NN) {
        g_accio[i].a = make_float4(0.f, 0.f, 0.f, 0.f);
        g_accio[i].b = make_float2(0.f, 0.f);
        g_den_env[i] = 0.f;
    }
    if (i == 0) g_ecnt = 0;
}

// s_rel (+a_b) for all three layers.
__global__ void k_srel(const float* __restrict__ iWr, const float* __restrict__ iWrb,
                       const float* __restrict__ ia, const float* __restrict__ iab,
                       const float* __restrict__ irel, const float* __restrict__ oWr,
                       const float* __restrict__ oWrb, const float* __restrict__ oa,
                       const float* __restrict__ oab, const float* __restrict__ orel,
                       const float* __restrict__ eWr, const float* __restrict__ eWrb,
                       const float* __restrict__ ea, const float* __restrict__ eab,
                       const float* __restrict__ erel) {
    __shared__ float red[128];
    int j = threadIdx.x;
    for (int t = 0; t < 2; t++) {
        float r = eWrb[j];
        for (int k = 0; k < 100; k++) r += erel[t * 100 + k] * eWr[j * 100 + k];
        red[j] = r * ea[256 + j];
        __syncthreads();
        for (int s = 64; s > 0; s >>= 1) {
            if (j < s) red[j] += red[j + s];
            __syncthreads();
        }
        if (j == 0) g_srel[4 + t] = red[0] + eab[0];
        __syncthreads();
    }
    if (j == 0) {
        for (int t = 0; t < 2; t++) {
            float r0 = iWrb[0], r1 = iWrb[1];
            for (int k = 0; k < 100; k++) {
                r0 += irel[t * 100 + k] * iWr[k];
                r1 += irel[t * 100 + k] * iWr[100 + k];
            }
            g_srel[t] = r0 * ia[4] + r1 * ia[5] + iab[0];
            float q0 = oWrb[0], q1 = oWrb[1];
            for (int k = 0; k < 100; k++) {
                q0 += orel[t * 100 + k] * oWr[k];
                q1 += orel[t * 100 + k] * oWr[100 + k];
            }
            g_srel[2 + t] = q0 * oa[4] + q1 * oa[5] + oab[0];
        }
    }
}

// per-node small layers (inA / outA). Writes ONLY the fields it owns (scalar
// stores) so it can run concurrently with k_mma, which owns dstv.z and src.B.x.
__global__ void k_node_small(const float* __restrict__ x, const float* __restrict__ iW,
                             const float* __restrict__ iWb, const float* __restrict__ ia,
                             const float* __restrict__ iRw, const float* __restrict__ iRb,
                             const float* __restrict__ oW, const float* __restrict__ oWb,
                             const float* __restrict__ oa, const float* __restrict__ oRw,
                             const float* __restrict__ oRb) {
    int warp = (blockIdx.x * blockDim.x + threadIdx.x) >> 5;
    int lane = threadIdx.x & 31;
    if (warp >= NN) return;
    float4 xv = *(const float4*)(x + warp * 128 + lane * 4);
    auto dotw = [&](const float* w) {
        float4 wv = *(const float4*)(w + lane * 4);
        return xv.x * wv.x + xv.y * wv.y + xv.z * wv.z + xv.w * wv.w;
    };
    float d0 = dotw(iW), d1 = dotw(iW + 128);
    float d2 = dotw(iRw), d3 = dotw(iRw + 128);
    float d4 = dotw(oW), d5 = dotw(oW + 128);
    float d6 = dotw(oRw), d7 = dotw(oRw + 128);
    auto wred = [&](float v) {
        for (int o = 16; o > 0; o >>= 1) v += __shfl_xor_sync(0xffffffffu, v, o);
        return v;
    };
    d0 = wred(d0); d1 = wred(d1); d2 = wred(d2); d3 = wred(d3);
    d4 = wred(d4); d5 = wred(d5); d6 = wred(d6); d7 = wred(d7);
    if (lane == 0) {
        float h0 = d0 + iWb[0], h1 = d1 + iWb[1];
        float p0 = d4 + oWb[0], p1 = d5 + oWb[1];
        float* dv = (float*)(g_dstv + warp);
        dv[0] = h0 * ia[0] + h1 * ia[1];
        dv[1] = p0 * oa[0] + p1 * oa[1];
        g_src[warp].A = make_float4(h0 * ia[2] + h1 * ia[3], p0 * oa[2] + p1 * oa[3], h0, h1);
        float* sB = (float*)&g_src[warp].B;
        sB[1] = p0;
        sB[2] = p1;
        g_res_in[warp] = make_float2(d2 + iRb[0], d3 + iRb[1]);
        g_res_out[warp] = make_float2(d6 + oRb[0], d7 + oRb[1]);
    }
}

// ---------------- tensor-core env GEMMs (bf16x3 via warp mma.sync, fused) ----------------
// One CTA (256 threads, 8 warps): converts A once, runs h_env = x@W^T+b (+ fused
// s_env) AND d_out = x@Wres^T+b. D = A_hi*B_hi + A_hi*B_lo + A_lo*B_hi.
#define OFF_BW 64
#define OFF_BR 576
#define OFF_A1 1088
#define OFF_A2 1600
#define OFF_AHI 2176
#define TILE_B (128 * 272)  // 128 rows x (128 bf16 + 8 pad) = 34816 B
#define OFF_ALO (OFF_AHI + TILE_B)
#define OFF_WHI (OFF_ALO + TILE_B)
#define OFF_WLO (OFF_WHI + TILE_B)
#define OFF_RHI (OFF_WLO + TILE_B)
#define OFF_RLO (OFF_RHI + TILE_B)
#define OFF_SD (OFF_RLO + TILE_B)  // 128*2 floats
#define OFF_SS (OFF_SD + 1024)     // 128*2 floats
#define SMEM_MMA (OFF_SS + 1024)

__device__ __forceinline__ void cvt_tile(const float* __restrict__ T, char* smem, int off_hi,
                                         int off_lo, int tid, int m0, bool guard) {
#pragma unroll
    for (int i = 0; i < 16; i++) {
        int f = i * 256 + tid;  // float4 index in 128x32
        int row = f >> 5;
        int c4 = f & 31;
        float4 v;
        if (guard) {
            int gm = m0 + row;
            v = (gm < NN) ? *(const float4*)(T + (long)gm * 128 + c4 * 4)
                          : make_float4(0.f, 0.f, 0.f, 0.f);
        } else {
            v = *(const float4*)(T + (long)row * 128 + c4 * 4);
        }
        unsigned short h0 = f2b(v.x), h1 = f2b(v.y), h2 = f2b(v.z), h3 = f2b(v.w);
        uint32_t hi01 = (uint32_t)h0 | ((uint32_t)h1 << 16);
        uint32_t hi23 = (uint32_t)h2 | ((uint32_t)h3 << 16);
        uint32_t lo01 = (uint32_t)f2b(v.x - __bfloat162float(__ushort_as_bfloat16(h0))) |
                        ((uint32_t)f2b(v.y - __bfloat162float(__ushort_as_bfloat16(h1))) << 16);
        uint32_t lo23 = (uint32_t)f2b(v.z - __bfloat162float(__ushort_as_bfloat16(h2))) |
                        ((uint32_t)f2b(v.w - __bfloat162float(__ushort_as_bfloat16(h3))) << 16);
        char* p = smem + row * 272 + c4 * 8;
        *(uint32_t*)(p + off_hi) = hi01;
        *(uint32_t*)(p + off_hi + 4) = hi23;
        *(uint32_t*)(p + off_lo) = lo01;
        *(uint32_t*)(p + off_lo + 4) = lo23;
    }
}

__global__ void __launch_bounds__(256, 1)
k_mma(const float* __restrict__ A, const float* __restrict__ W0, const float* __restrict__ b0,
      const float* __restrict__ W1, const float* __restrict__ b1, float* __restrict__ Cout,
      const float* __restrict__ ea) {
    extern __shared__ char smem[];
    const int m0 = blockIdx.x * 128;
    const int tid = threadIdx.x;
    const int wid = tid >> 5;
    const int lane = tid & 31;

    float* bw_s = (float*)(smem + OFF_BW);
    float* br_s = (float*)(smem + OFF_BR);
    float* a1_s = (float*)(smem + OFF_A1);
    float* a2_s = (float*)(smem + OFF_A2);
    if (tid < 128) {
        bw_s[tid] = b0[tid];
        br_s[tid] = b1[tid];
        a1_s[tid] = ea[tid];
        a2_s[tid] = ea[128 + tid];
    }

    cvt_tile(A, smem, OFF_AHI, OFF_ALO, tid, m0, true);
    cvt_tile(W0, smem, OFF_WHI, OFF_WLO, tid, 0, false);
    cvt_tile(W1, smem, OFF_RHI, OFF_RLO, tid, 0, false);
    __syncthreads();

    // warp layout: 4 (m) x 2 (n); warp tile 32x64
    const int wm = wid >> 1;
    const int wn = wid & 1;
    const uint32_t sb = smem_u32(smem);
    const int a_row = lane & 15;
    const int a_kb = (lane >> 4) * 16;
    const int b_n = (lane & 7) + ((lane >> 4) << 3);
    const int b_kb = ((lane >> 3) & 1) * 16;
    const int fr = lane >> 2;
    const int fc = (lane & 3) * 2;

    float* sdbuf = (float*)(smem + OFF_SD);
    float* ssbuf = (float*)(smem + OFF_SS);

#pragma unroll
    for (int gemm = 0; gemm < 2; gemm++) {
        const bool env = (gemm == 0);
        float* C = env ? g_h_env : Cout;
        const float* bias_s = env ? bw_s : br_s;
        const int off_bh = env ? OFF_WHI : OFF_RHI;
        const int off_bl = env ? OFF_WLO : OFF_RLO;

        float acc[2][8][4];
#pragma unroll
        for (int ms = 0; ms < 2; ms++)
#pragma unroll
            for (int ns = 0; ns < 8; ns++)
#pragma unroll
                for (int q = 0; q < 4; q++) acc[ms][ns][q] = 0.f;

#pragma unroll
        for (int pass = 0; pass < 3; pass++) {
            const uint32_t abase = sb + (pass == 2 ? OFF_ALO : OFF_AHI);
            const uint32_t bbase = sb + (pass == 1 ? off_bl : off_bh);
#pragma unroll
            for (int kk = 0; kk < 8; kk++) {
                uint32_t af[2][4];
#pragma unroll
                for (int ms = 0; ms < 2; ms++) {
                    uint32_t addr = abase + (wm * 32 + ms * 16 + a_row) * 272 + kk * 32 + a_kb;
                    ldm4(af[ms], addr);
                }
                uint32_t bf[8][2];
#pragma unroll
                for (int np = 0; np < 4; np++) {
                    uint32_t addr = bbase + (wn * 64 + np * 16 + b_n) * 272 + kk * 32 + b_kb;
                    uint32_t r[4];
                    ldm4(r, addr);
                    bf[np * 2][0] = r[0];
                    bf[np * 2][1] = r[1];
                    bf[np * 2 + 1][0] = r[2];
                    bf[np * 2 + 1][1] = r[3];
                }
#pragma unroll
                for (int ms = 0; ms < 2; ms++)
#pragma unroll
                    for (int ns = 0; ns < 8; ns++) mma_bf16(acc[ms][ns], af[ms], bf[ns]);
            }
        }

        // epilogue: bias + direct float2 stores (quad-contiguous 32B sectors) + fused dots
#pragma unroll
        for (int ms = 0; ms < 2; ms++) {
#pragma unroll
            for (int h = 0; h < 2; h++) {
                int row = wm * 32 + ms * 16 + h * 8 + fr;
                int gm = m0 + row;
                float sd = 0.f, ss = 0.f;
#pragma unroll
                for (int ns = 0; ns < 8; ns++) {
                    int col = wn * 64 + ns * 8 + fc;
                    float v0 = acc[ms][ns][h * 2 + 0] + bias_s[col];
                    float v1 = acc[ms][ns][h * 2 + 1] + bias_s[col + 1];
                    if (gm < NN) {
                        float2 st = make_float2(v0, v1);
                        *(float2*)(C + (long)gm * 128 + col) = st;
                    }
                    if (env) {
                        sd += v0 * a1_s[col] + v1 * a1_s[col + 1];
                        ss += v0 * a2_s[col] + v1 * a2_s[col + 1];
                    }
                }
                if (env) {
                    sd += __shfl_xor_sync(0xffffffffu, sd, 1);
                    sd += __shfl_xor_sync(0xffffffffu, sd, 2);
                    ss += __shfl_xor_sync(0xffffffffu, ss, 1);
                    ss += __shfl_xor_sync(0xffffffffu, ss, 2);
                    if ((lane & 3) == 0) {
                        sdbuf[row * 2 + wn] = sd;
                        ssbuf[row * 2 + wn] = ss;
                    }
                }
            }
        }
        if (env) {
            __syncthreads();
            if (tid < 128 && m0 + tid < NN) {
                ((float*)(g_dstv + m0 + tid))[2] = sdbuf[tid * 2] + sdbuf[tid * 2 + 1];
                ((float*)&g_src[m0 + tid].B)[0] = ssbuf[tid * 2] + ssbuf[tid * 2 + 1];
            }
        }
    }
}

// Fused edge pass: logits for all three layers, exp (shift-free softmax —
// alpha = e/sum(e) is shift-invariant and |logit| is small), vector scatter-reduce.
__global__ void k_edge_fused(const int* __restrict__ ei, const int* __restrict__ et) {
    int e = blockIdx.x * blockDim.x + threadIdx.x;
    if (e >= EE) return;
    float s0 = g_srel[0], s1 = g_srel[1], s2 = g_srel[2];
    float s3 = g_srel[3], s4 = g_srel[4], s5 = g_srel[5];
    int src = ei[e];
    int dst = ei[EE + e];
    int t = et[e];
    float4 dv = g_dstv[dst];
    float4 sa = g_src[src].A;
    float4 sb = g_src[src].B;
    float win = expf(lrelu(dv.x + sa.x + (t ? s1 : s0)));
    float wout = expf(lrelu(dv.y + sa.y + (t ? s3 : s2)));
    float wenv = expf(lrelu(dv.z + sb.x + (t ? s5 : s4)));
    red_add_v4(&g_accio[dst].a.x, win, sa.z * win, sa.w * win, wout);
    red_add_v2(&g_accio[dst].b.x, sb.y * wout, sb.z * wout);
    g_Wenv[e] = wenv;
}

// gumbel-hard choices
__global__ void k_choice(const float* __restrict__ gin, const float* __restrict__ gout) {
    int i = blockIdx.x * blockDim.x + threadIdx.x;
    if (i >= NN) return;
    float4 a = g_accio[i].a;
    float2 b = g_accio[i].b;
    {
        float dn = fmaxf(a.x, 1e-16f);
        float2 rs = g_res_in[i];
        float z0 = a.y / dn + rs.x + gin[2 * i];
        float z1 = a.z / dn + rs.y + gin[2 * i + 1];
        g_cin[i] = (z0 >= z1) ? 1 : 0;
    }
    {
        float dn = fmaxf(a.w, 1e-16f);
        float2 rs = g_res_out[i];
        float z0 = b.x / dn + rs.x + gout[2 * i];
        float z1 = b.y / dn + rs.y + gout[2 * i + 1];
        g_cout[i] = (z0 >= z1) ? 1 : 0;
    }
}

// env: apply mask, accumulate denominator, compact survivors
__global__ void k_edge_mask(const int* __restrict__ ei) {
    int e = blockIdx.x * blockDim.x + threadIdx.x;
    bool keep = false;
    if (e < EE) {
        int src = ei[e];
        int dst = ei[EE + e];
        keep = g_cin[dst] && g_cout[src];
        if (keep) atomicAdd(&g_den_env[dst], g_Wenv[e]);
    }
    unsigned bal = __ballot_sync(0xffffffffu, keep);
    if (keep) {
        int lane = threadIdx.x & 31;
        int leader = __ffs(bal) - 1;
        int base;
        if (lane == leader) base = atomicAdd(&g_ecnt, __popc(bal));
        base = __shfl_sync(bal, base, leader);
        int off = __popc(bal & ((1u << lane) - 1u));
        g_elist[base + off] = e;
    }
}

// env aggregation over compacted edges: warp per edge, persistent grid-stride
__global__ void k_edge_aggr(const int* __restrict__ ei) {
    const int cnt = g_ecnt;
    int warp = (blockIdx.x * blockDim.x + threadIdx.x) >> 5;
    const int nwarps = (gridDim.x * blockDim.x) >> 5;
    const int lane = threadIdx.x & 31;
    for (int i = warp; i < cnt; i += nwarps) {
        int e = g_elist[i];
        int src = ei[e];
        int dst = ei[EE + e];
        float w = g_Wenv[e];
        float4 hv = *(const float4*)(g_h_env + (long)src * 128 + lane * 4);
        red_add_v4(g_num_env + (long)dst * 128 + lane * 4, hv.x * w, hv.y * w, hv.z * w,
                   hv.w * w);
    }
}

// out = res (already in d_out) + num/max(den,1e-16)
__global__ void k_final(float* __restrict__ out) {
    int idx = blockIdx.x * blockDim.x + threadIdx.x;
    if (idx >= NN * 32) return;
    int node = idx >> 5;
    float inv = 1.f / fmaxf(g_den_env[node], 1e-16f);
    float4 nm = ((const float4*)g_num_env)[idx];
    float4 o = ((float4*)out)[idx];
    o.x += nm.x * inv;
    o.y += nm.y * inv;
    o.z += nm.z * inv;
    o.w += nm.w * inv;
    ((float4*)out)[idx] = o;
}

// ---------------- launch ----------------
extern "C" void kernel_launch(void* const* d_in, const int* in_sizes, int n_in, void* d_out,
                              int out_size) {
    const float* x = (const float*)d_in[0];
    const int* ei = (const int*)d_in[1];
    const int* et = (const int*)d_in[2];
    const float* gin = (const float*)d_in[3];
    const float* gout = (const float*)d_in[4];
    const float* iW = (const float*)d_in[5];
    const float* iWb = (const float*)d_in[6];
    const float* ia = (const float*)d_in[9];
    const float* iRw = (const float*)d_in[11];
    const float* iRb = (const float*)d_in[12];
    const float* oW = (const float*)d_in[14];
    const float* oWb = (const float*)d_in[15];
    const float* oa = (const float*)d_in[18];
    const float* oRw = (const float*)d_in[20];
    const float* oRb = (const float*)d_in[21];
    const float* eW = (const float*)d_in[23];
    const float* eWb = (const float*)d_in[24];
    const float* ea = (const float*)d_in[27];
    const float* eRw = (const float*)d_in[29];
    const float* eRb = (const float*)d_in[30];
    float* out = (float*)d_out;

    static cudaStream_t s1 = nullptr;
    static cudaEvent_t evFork = nullptr, evJoin = nullptr;
    if (s1 == nullptr) {
        cudaStreamCreateWithFlags(&s1, cudaStreamNonBlocking);
        cudaEventCreateWithFlags(&evFork, cudaEventDisableTiming);
        cudaEventCreateWithFlags(&evJoin, cudaEventDisableTiming);
        cudaFuncSetAttribute(k_mma, cudaFuncAttributeMaxDynamicSharedMemorySize, SMEM_MMA);
    }

    // fork: front-end (init/srel/node_small) runs on s1 concurrently with k_mma
    cudaEventRecord(evFork, 0);
    cudaStreamWaitEvent(s1, evFork, 0);
    k_init<<<(NN * 128 + 255) / 256, 256, 0, s1>>>();
    k_srel<<<1, 128, 0, s1>>>((const float*)d_in[7], (const float*)d_in[8], ia,
                              (const float*)d_in[10], (const float*)d_in[13],
                              (const float*)d_in[16], (const float*)d_in[17], oa,
                              (const float*)d_in[19], (const float*)d_in[22],
                              (const float*)d_in[25], (const float*)d_in[26], ea,
                              (const float*)d_in[28], (const float*)d_in[31]);
    k_node_small<<<(NN + 7) / 8, 256, 0, s1>>>(x, iW, iWb, ia, iRw, iRb, oW, oWb, oa, oRw,
                                               oRb);
    cudaEventRecord(evJoin, s1);

    k_mma<<<(NN + 127) / 128, 256, SMEM_MMA>>>(x, eW, eWb, eRw, eRb, out, ea);
    cudaStreamWaitEvent(0, evJoin, 0);

    k_edge_fused<<<(EE + 255) / 256, 256>>>(ei, et);
    k_choice<<<(NN + 255) / 256, 256>>>(gin, gout);
    k_edge_mask<<<(EE + 255) / 256, 256>>>(ei);
    k_edge_aggr<<<2048, 256>>>(ei);
    k_final<<<(NN * 32 + 255) / 256, 256>>>(out);
}

// round 17
// speedup vs baseline: 1.4112x; 1.3119x over previous
#include <cuda_runtime.h>
#include <cuda_bf16.h>
#include <math.h>
#include <cstdint>

#define NN 50000
#define EE 640000

// ---------------- scratch (device globals; no allocation allowed) ----------------
__device__ __align__(16) float g_h_env[NN * 128];  // h for env layer
__device__ float g_Wenv[EE];  // exp(env logit) per edge
__device__ int g_elist[EE];   // compacted surviving env edges
__device__ int g_ecnt;

// packed per-node gather vectors
__device__ __align__(16) float4 g_dstv[NN];  // {sd_in, sd_out, sd_env, -}
struct __align__(32) SrcPack {
    float4 A;  // {ss_in, ss_out, h_in.x, h_in.y}
    float4 B;  // {ss_env, h_out.x, h_out.y, -}
};
__device__ SrcPack g_src[NN];

// packed per-node in/out accumulators (vector reductions land here)
struct __align__(32) AccIO {
    float4 a;  // {den_in, num_in.x, num_in.y, den_out}
    float2 b;  // {num_out.x, num_out.y}
    float2 pad;
};
__device__ AccIO g_accio[NN];

__device__ float2 g_res_in[NN], g_res_out[NN];
__device__ float g_den_env[NN];
__device__ unsigned char g_cin[NN], g_cout[NN];
__device__ float g_srel[6];  // (in,out,env) s_rel[t] + a_b, t in {0,1}

// ---------------- helpers ----------------
__device__ __forceinline__ float lrelu(float v) { return v >= 0.f ? v : 0.2f * v; }

__device__ __forceinline__ void red_add_v2(float* p, float a, float b) {
    asm volatile("red.global.add.v2.f32 [%0], {%1, %2};" ::"l"(p), "f"(a), "f"(b) : "memory");
}
__device__ __forceinline__ void red_add_v4(float* p, float a, float b, float c, float d) {
    asm volatile("red.global.add.v4.f32 [%0], {%1, %2, %3, %4};" ::"l"(p), "f"(a), "f"(b),
                 "f"(c), "f"(d)
                 : "memory");
}

__device__ __forceinline__ uint32_t smem_u32(const void* p) {
    uint32_t a;
    asm("{ .reg .u64 t; cvta.to.shared.u64 t, %1; cvt.u32.u64 %0, t; }" : "=r"(a) : "l"(p));
    return a;
}
__device__ __forceinline__ unsigned short f2b(float v) {
    return __bfloat16_as_ushort(__float2bfloat16_rn(v));
}
__device__ __forceinline__ void ldm4(uint32_t* r, uint32_t addr) {
    asm volatile("ldmatrix.sync.aligned.m8n8.x4.shared.b16 {%0,%1,%2,%3}, [%4];"
                 : "=r"(r[0]), "=r"(r[1]), "=r"(r[2]), "=r"(r[3])
                 : "r"(addr));
}
__device__ __forceinline__ void mma_bf16(float* c, const uint32_t* a, const uint32_t* b) {
    asm volatile(
        "mma.sync.aligned.m16n8k16.row.col.f32.bf16.bf16.f32 "
        "{%0,%1,%2,%3}, {%4,%5,%6,%7}, {%8,%9}, {%0,%1,%2,%3};"
        : "+f"(c[0]), "+f"(c[1]), "+f"(c[2]), "+f"(c[3])
        : "r"(a[0]), "r"(a[1]), "r"(a[2]), "r"(a[3]), "r"(b[0]), "r"(b[1]));
}

// ---------------- kernels ----------------
__global__ void k_init() {
    int i = blockIdx.x * blockDim.x + threadIdx.x;
    if (i < NN) {
        g_accio[i].a = make_float4(0.f, 0.f, 0.f, 0.f);
        g_accio[i].b = make_float2(0.f, 0.f);
        g_den_env[i] = 0.f;
    }
    if (i == 0) g_ecnt = 0;
}

// s_rel (+a_b) for all three layers.
__global__ void k_srel(const float* __restrict__ iWr, const float* __restrict__ iWrb,
                       const float* __restrict__ ia, const float* __restrict__ iab,
                       const float* __restrict__ irel, const float* __restrict__ oWr,
                       const float* __restrict__ oWrb, const float* __restrict__ oa,
                       const float* __restrict__ oab, const float* __restrict__ orel,
                       const float* __restrict__ eWr, const float* __restrict__ eWrb,
                       const float* __restrict__ ea, const float* __restrict__ eab,
                       const float* __restrict__ erel) {
    __shared__ float red[128];
    int j = threadIdx.x;
    for (int t = 0; t < 2; t++) {
        float r = eWrb[j];
        for (int k = 0; k < 100; k++) r += erel[t * 100 + k] * eWr[j * 100 + k];
        red[j] = r * ea[256 + j];
        __syncthreads();
        for (int s = 64; s > 0; s >>= 1) {
            if (j < s) red[j] += red[j + s];
            __syncthreads();
        }
        if (j == 0) g_srel[4 + t] = red[0] + eab[0];
        __syncthreads();
    }
    if (j == 0) {
        for (int t = 0; t < 2; t++) {
            float r0 = iWrb[0], r1 = iWrb[1];
            for (int k = 0; k < 100; k++) {
                r0 += irel[t * 100 + k] * iWr[k];
                r1 += irel[t * 100 + k] * iWr[100 + k];
            }
            g_srel[t] = r0 * ia[4] + r1 * ia[5] + iab[0];
            float q0 = oWrb[0], q1 = oWrb[1];
            for (int k = 0; k < 100; k++) {
                q0 += orel[t * 100 + k] * oWr[k];
                q1 += orel[t * 100 + k] * oWr[100 + k];
            }
            g_srel[2 + t] = q0 * oa[4] + q1 * oa[5] + oab[0];
        }
    }
}

// per-node small layers (inA / outA). Writes ONLY the fields it owns (scalar
// stores) so it can run concurrently with k_mma, which owns dstv.z and src.B.x.
__global__ void k_node_small(const float* __restrict__ x, const float* __restrict__ iW,
                             const float* __restrict__ iWb, const float* __restrict__ ia,
                             const float* __restrict__ iRw, const float* __restrict__ iRb,
                             const float* __restrict__ oW, const float* __restrict__ oWb,
                             const float* __restrict__ oa, const float* __restrict__ oRw,
                             const float* __restrict__ oRb) {
    int warp = (blockIdx.x * blockDim.x + threadIdx.x) >> 5;
    int lane = threadIdx.x & 31;
    if (warp >= NN) return;
    float4 xv = *(const float4*)(x + warp * 128 + lane * 4);
    auto dotw = [&](const float* w) {
        float4 wv = *(const float4*)(w + lane * 4);
        return xv.x * wv.x + xv.y * wv.y + xv.z * wv.z + xv.w * wv.w;
    };
    float d0 = dotw(iW), d1 = dotw(iW + 128);
    float d2 = dotw(iRw), d3 = dotw(iRw + 128);
    float d4 = dotw(oW), d5 = dotw(oW + 128);
    float d6 = dotw(oRw), d7 = dotw(oRw + 128);
    auto wred = [&](float v) {
        for (int o = 16; o > 0; o >>= 1) v += __shfl_xor_sync(0xffffffffu, v, o);
        return v;
    };
    d0 = wred(d0); d1 = wred(d1); d2 = wred(d2); d3 = wred(d3);
    d4 = wred(d4); d5 = wred(d5); d6 = wred(d6); d7 = wred(d7);
    if (lane == 0) {
        float h0 = d0 + iWb[0], h1 = d1 + iWb[1];
        float p0 = d4 + oWb[0], p1 = d5 + oWb[1];
        float* dv = (float*)(g_dstv + warp);
        dv[0] = h0 * ia[0] + h1 * ia[1];
        dv[1] = p0 * oa[0] + p1 * oa[1];
        g_src[warp].A = make_float4(h0 * ia[2] + h1 * ia[3], p0 * oa[2] + p1 * oa[3], h0, h1);
        float* sB = (float*)&g_src[warp].B;
        sB[1] = p0;
        sB[2] = p1;
        g_res_in[warp] = make_float2(d2 + iRb[0], d3 + iRb[1]);
        g_res_out[warp] = make_float2(d6 + oRb[0], d7 + oRb[1]);
    }
}

// ---------------- tensor-core env GEMMs (bf16x3 via warp mma.sync, fused) ----------------
// One CTA (256 threads, 8 warps): converts A once, runs h_env = x@W^T+b (+ fused
// s_env) AND d_out = x@Wres^T+b. D = A_hi*B_hi + A_hi*B_lo + A_lo*B_hi.
#define OFF_BW 64
#define OFF_BR 576
#define OFF_A1 1088
#define OFF_A2 1600
#define OFF_AHI 2176
#define TILE_B (128 * 272)  // 128 rows x (128 bf16 + 8 pad) = 34816 B
#define OFF_ALO (OFF_AHI + TILE_B)
#define OFF_WHI (OFF_ALO + TILE_B)
#define OFF_WLO (OFF_WHI + TILE_B)
#define OFF_RHI (OFF_WLO + TILE_B)
#define OFF_RLO (OFF_RHI + TILE_B)
#define OFF_SD (OFF_RLO + TILE_B)  // 128*2 floats
#define OFF_SS (OFF_SD + 1024)     // 128*2 floats
#define SMEM_MMA (OFF_SS + 1024)

__device__ __forceinline__ void cvt_tile(const float* __restrict__ T, char* smem, int off_hi,
                                         int off_lo, int tid, int m0, bool guard) {
#pragma unroll
    for (int i = 0; i < 16; i++) {
        int f = i * 256 + tid;  // float4 index in 128x32
        int row = f >> 5;
        int c4 = f & 31;
        float4 v;
        if (guard) {
            int gm = m0 + row;
            v = (gm < NN) ? *(const float4*)(T + (long)gm * 128 + c4 * 4)
                          : make_float4(0.f, 0.f, 0.f, 0.f);
        } else {
            v = *(const float4*)(T + (long)row * 128 + c4 * 4);
        }
        unsigned short h0 = f2b(v.x), h1 = f2b(v.y), h2 = f2b(v.z), h3 = f2b(v.w);
        uint32_t hi01 = (uint32_t)h0 | ((uint32_t)h1 << 16);
        uint32_t hi23 = (uint32_t)h2 | ((uint32_t)h3 << 16);
        uint32_t lo01 = (uint32_t)f2b(v.x - __bfloat162float(__ushort_as_bfloat16(h0))) |
                        ((uint32_t)f2b(v.y - __bfloat162float(__ushort_as_bfloat16(h1))) << 16);
        uint32_t lo23 = (uint32_t)f2b(v.z - __bfloat162float(__ushort_as_bfloat16(h2))) |
                        ((uint32_t)f2b(v.w - __bfloat162float(__ushort_as_bfloat16(h3))) << 16);
        char* p = smem + row * 272 + c4 * 8;
        *(uint32_t*)(p + off_hi) = hi01;
        *(uint32_t*)(p + off_hi + 4) = hi23;
        *(uint32_t*)(p + off_lo) = lo01;
        *(uint32_t*)(p + off_lo + 4) = lo23;
    }
}

__global__ void __launch_bounds__(256, 1)
k_mma(const float* __restrict__ A, const float* __restrict__ W0, const float* __restrict__ b0,
      const float* __restrict__ W1, const float* __restrict__ b1, float* __restrict__ Cout,
      const float* __restrict__ ea) {
    extern __shared__ char smem[];
    const int m0 = blockIdx.x * 128;
    const int tid = threadIdx.x;
    const int wid = tid >> 5;
    const int lane = tid & 31;

    float* bw_s = (float*)(smem + OFF_BW);
    float* br_s = (float*)(smem + OFF_BR);
    float* a1_s = (float*)(smem + OFF_A1);
    float* a2_s = (float*)(smem + OFF_A2);
    if (tid < 128) {
        bw_s[tid] = b0[tid];
        br_s[tid] = b1[tid];
        a1_s[tid] = ea[tid];
        a2_s[tid] = ea[128 + tid];
    }

    cvt_tile(A, smem, OFF_AHI, OFF_ALO, tid, m0, true);
    cvt_tile(W0, smem, OFF_WHI, OFF_WLO, tid, 0, false);
    cvt_tile(W1, smem, OFF_RHI, OFF_RLO, tid, 0, false);
    __syncthreads();

    // warp layout: 4 (m) x 2 (n); warp tile 32x64
    const int wm = wid >> 1;
    const int wn = wid & 1;
    const uint32_t sb = smem_u32(smem);
    const int a_row = lane & 15;
    const int a_kb = (lane >> 4) * 16;
    const int b_n = (lane & 7) + ((lane >> 4) << 3);
    const int b_kb = ((lane >> 3) & 1) * 16;
    const int fr = lane >> 2;
    const int fc = (lane & 3) * 2;

    float* sdbuf = (float*)(smem + OFF_SD);
    float* ssbuf = (float*)(smem + OFF_SS);

#pragma unroll
    for (int gemm = 0; gemm < 2; gemm++) {
        const bool env = (gemm == 0);
        float* C = env ? g_h_env : Cout;
        const float* bias_s = env ? bw_s : br_s;
        const int off_bh = env ? OFF_WHI : OFF_RHI;
        const int off_bl = env ? OFF_WLO : OFF_RLO;

        float acc[2][8][4];
#pragma unroll
        for (int ms = 0; ms < 2; ms++)
#pragma unroll
            for (int ns = 0; ns < 8; ns++)
#pragma unroll
                for (int q = 0; q < 4; q++) acc[ms][ns][q] = 0.f;

#pragma unroll
        for (int pass = 0; pass < 3; pass++) {
            const uint32_t abase = sb + (pass == 2 ? OFF_ALO : OFF_AHI);
            const uint32_t bbase = sb + (pass == 1 ? off_bl : off_bh);
#pragma unroll
            for (int kk = 0; kk < 8; kk++) {
                uint32_t af[2][4];
#pragma unroll
                for (int ms = 0; ms < 2; ms++) {
                    uint32_t addr = abase + (wm * 32 + ms * 16 + a_row) * 272 + kk * 32 + a_kb;
                    ldm4(af[ms], addr);
                }
                uint32_t bf[8][2];
#pragma unroll
                for (int np = 0; np < 4; np++) {
                    uint32_t addr = bbase + (wn * 64 + np * 16 + b_n) * 272 + kk * 32 + b_kb;
                    uint32_t r[4];
                    ldm4(r, addr);
                    bf[np * 2][0] = r[0];
                    bf[np * 2][1] = r[1];
                    bf[np * 2 + 1][0] = r[2];
                    bf[np * 2 + 1][1] = r[3];
                }
#pragma unroll
                for (int ms = 0; ms < 2; ms++)
#pragma unroll
                    for (int ns = 0; ns < 8; ns++) mma_bf16(acc[ms][ns], af[ms], bf[ns]);
            }
        }

        // epilogue: bias + direct float2 stores (quad-contiguous 32B sectors) + fused dots
#pragma unroll
        for (int ms = 0; ms < 2; ms++) {
#pragma unroll
            for (int h = 0; h < 2; h++) {
                int row = wm * 32 + ms * 16 + h * 8 + fr;
                int gm = m0 + row;
                float sd = 0.f, ss = 0.f;
#pragma unroll
                for (int ns = 0; ns < 8; ns++) {
                    int col = wn * 64 + ns * 8 + fc;
                    float v0 = acc[ms][ns][h * 2 + 0] + bias_s[col];
                    float v1 = acc[ms][ns][h * 2 + 1] + bias_s[col + 1];
                    if (gm < NN) {
                        float2 st = make_float2(v0, v1);
                        *(float2*)(C + (long)gm * 128 + col) = st;
                    }
                    if (env) {
                        sd += v0 * a1_s[col] + v1 * a1_s[col + 1];
                        ss += v0 * a2_s[col] + v1 * a2_s[col + 1];
                    }
                }
                if (env) {
                    sd += __shfl_xor_sync(0xffffffffu, sd, 1);
                    sd += __shfl_xor_sync(0xffffffffu, sd, 2);
                    ss += __shfl_xor_sync(0xffffffffu, ss, 1);
                    ss += __shfl_xor_sync(0xffffffffu, ss, 2);
                    if ((lane & 3) == 0) {
                        sdbuf[row * 2 + wn] = sd;
                        ssbuf[row * 2 + wn] = ss;
                    }
                }
            }
        }
        if (env) {
            __syncthreads();
            if (tid < 128 && m0 + tid < NN) {
                ((float*)(g_dstv + m0 + tid))[2] = sdbuf[tid * 2] + sdbuf[tid * 2 + 1];
                ((float*)&g_src[m0 + tid].B)[0] = ssbuf[tid * 2] + ssbuf[tid * 2 + 1];
            }
        }
    }
}

// Fused edge pass: logits for all three layers, exp (shift-free softmax —
// alpha = e/sum(e) is shift-invariant and |logit| is small), vector scatter-reduce.
__global__ void k_edge_fused(const int* __restrict__ ei, const int* __restrict__ et) {
    int e = blockIdx.x * blockDim.x + threadIdx.x;
    if (e >= EE) return;
    float s0 = g_srel[0], s1 = g_srel[1], s2 = g_srel[2];
    float s3 = g_srel[3], s4 = g_srel[4], s5 = g_srel[5];
    int src = ei[e];
    int dst = ei[EE + e];
    int t = et[e];
    float4 dv = g_dstv[dst];
    float4 sa = g_src[src].A;
    float4 sb = g_src[src].B;
    float win = expf(lrelu(dv.x + sa.x + (t ? s1 : s0)));
    float wout = expf(lrelu(dv.y + sa.y + (t ? s3 : s2)));
    float wenv = expf(lrelu(dv.z + sb.x + (t ? s5 : s4)));
    red_add_v4(&g_accio[dst].a.x, win, sa.z * win, sa.w * win, wout);
    red_add_v2(&g_accio[dst].b.x, sb.y * wout, sb.z * wout);
    g_Wenv[e] = wenv;
}

// gumbel-hard choices
__global__ void k_choice(const float* __restrict__ gin, const float* __restrict__ gout) {
    int i = blockIdx.x * blockDim.x + threadIdx.x;
    if (i >= NN) return;
    float4 a = g_accio[i].a;
    float2 b = g_accio[i].b;
    {
        float dn = fmaxf(a.x, 1e-16f);
        float2 rs = g_res_in[i];
        float z0 = a.y / dn + rs.x + gin[2 * i];
        float z1 = a.z / dn + rs.y + gin[2 * i + 1];
        g_cin[i] = (z0 >= z1) ? 1 : 0;
    }
    {
        float dn = fmaxf(a.w, 1e-16f);
        float2 rs = g_res_out[i];
        float z0 = b.x / dn + rs.x + gout[2 * i];
        float z1 = b.y / dn + rs.y + gout[2 * i + 1];
        g_cout[i] = (z0 >= z1) ? 1 : 0;
    }
}

// env: apply mask, accumulate denominator, compact survivors
__global__ void k_edge_mask(const int* __restrict__ ei) {
    int e = blockIdx.x * blockDim.x + threadIdx.x;
    bool keep = false;
    if (e < EE) {
        int src = ei[e];
        int dst = ei[EE + e];
        keep = g_cin[dst] && g_cout[src];
        if (keep) atomicAdd(&g_den_env[dst], g_Wenv[e]);
    }
    unsigned bal = __ballot_sync(0xffffffffu, keep);
    if (keep) {
        int lane = threadIdx.x & 31;
        int leader = __ffs(bal) - 1;
        int base;
        if (lane == leader) base = atomicAdd(&g_ecnt, __popc(bal));
        base = __shfl_sync(bal, base, leader);
        int off = __popc(bal & ((1u << lane) - 1u));
        g_elist[base + off] = e;
    }
}

// env aggregation over compacted edges: warp per edge, persistent grid-stride.
// Normalization folded into the edge weight (den is final after k_edge_mask),
// reducing straight into d_out (which already holds the residual).
__global__ void k_edge_aggr(const int* __restrict__ ei, float* __restrict__ out) {
    const int cnt = g_ecnt;
    int warp = (blockIdx.x * blockDim.x + threadIdx.x) >> 5;
    const int nwarps = (gridDim.x * blockDim.x) >> 5;
    const int lane = threadIdx.x & 31;
    for (int i = warp; i < cnt; i += nwarps) {
        int e = g_elist[i];
        int src = ei[e];
        int dst = ei[EE + e];
        float winv = 0.f;
        if (lane == 0) winv = g_Wenv[e] / fmaxf(g_den_env[dst], 1e-16f);
        winv = __shfl_sync(0xffffffffu, winv, 0);
        float4 hv = *(const float4*)(g_h_env + (long)src * 128 + lane * 4);
        red_add_v4(out + (long)dst * 128 + lane * 4, hv.x * winv, hv.y * winv, hv.z * winv,
                   hv.w * winv);
    }
}

// ---------------- launch ----------------
extern "C" void kernel_launch(void* const* d_in, const int* in_sizes, int n_in, void* d_out,
                              int out_size) {
    const float* x = (const float*)d_in[0];
    const int* ei = (const int*)d_in[1];
    const int* et = (const int*)d_in[2];
    const float* gin = (const float*)d_in[3];
    const float* gout = (const float*)d_in[4];
    const float* iW = (const float*)d_in[5];
    const float* iWb = (const float*)d_in[6];
    const float* ia = (const float*)d_in[9];
    const float* iRw = (const float*)d_in[11];
    const float* iRb = (const float*)d_in[12];
    const float* oW = (const float*)d_in[14];
    const float* oWb = (const float*)d_in[15];
    const float* oa = (const float*)d_in[18];
    const float* oRw = (const float*)d_in[20];
    const float* oRb = (const float*)d_in[21];
    const float* eW = (const float*)d_in[23];
    const float* eWb = (const float*)d_in[24];
    const float* ea = (const float*)d_in[27];
    const float* eRw = (const float*)d_in[29];
    const float* eRb = (const float*)d_in[30];
    float* out = (float*)d_out;

    static cudaStream_t s1 = nullptr;
    static cudaEvent_t evFork = nullptr, evJoin = nullptr;
    if (s1 == nullptr) {
        cudaStreamCreateWithFlags(&s1, cudaStreamNonBlocking);
        cudaEventCreateWithFlags(&evFork, cudaEventDisableTiming);
        cudaEventCreateWithFlags(&evJoin, cudaEventDisableTiming);
        cudaFuncSetAttribute(k_mma, cudaFuncAttributeMaxDynamicSharedMemorySize, SMEM_MMA);
    }

    // fork: front-end (init/srel/node_small) runs on s1 concurrently with k_mma
    cudaEventRecord(evFork, 0);
    cudaStreamWaitEvent(s1, evFork, 0);
    k_init<<<(NN + 255) / 256, 256, 0, s1>>>();
    k_srel<<<1, 128, 0, s1>>>((const float*)d_in[7], (const float*)d_in[8], ia,
                              (const float*)d_in[10], (const float*)d_in[13],
                              (const float*)d_in[16], (const float*)d_in[17], oa,
                              (const float*)d_in[19], (const float*)d_in[22],
                              (const float*)d_in[25], (const float*)d_in[26], ea,
                              (const float*)d_in[28], (const float*)d_in[31]);
    k_node_small<<<(NN + 7) / 8, 256, 0, s1>>>(x, iW, iWb, ia, iRw, iRb, oW, oWb, oa, oRw,
                                               oRb);
    cudaEventRecord(evJoin, s1);

    k_mma<<<(NN + 127) / 128, 256, SMEM_MMA>>>(x, eW, eWb, eRw, eRb, out, ea);
    cudaStreamWaitEvent(0, evJoin, 0);

    k_edge_fused<<<(EE + 255) / 256, 256>>>(ei, et);
    k_choice<<<(NN + 255) / 256, 256>>>(gin, gout);
    k_edge_mask<<<(EE + 255) / 256, 256>>>(ei);
    k_edge_aggr<<<2048, 256>>>(ei, out);
}